// round 8
// baseline (speedup 1.0000x reference)
#include <cuda_runtime.h>

// Problem constants
#define NB 32
#define NH 480
#define NW 640
#define HW (NH * NW)            // 307200 pixels per channel plane
#define PIX4 (HW / 4)           // 76800 float4 pixels per plane
#define THREADS 256
#define BLOCKS_PER_IMG (PIX4 / THREADS)   // 300
#define GRID (NB * BLOCKS_PER_IMG)        // 9600

// Per-block partial sums — every slot is written every launch, no init needed.
__device__ float g_partial[GRID];

// ---------------------------------------------------------------------------
// Pass 1: per-block partial sum of gray(clip(x * bf)).
// Reads are DEFAULT policy so x stays L2-resident for pass 2.
// ---------------------------------------------------------------------------
__global__ void __launch_bounds__(THREADS)
reduce_mean_kernel(const float* __restrict__ x,
                   const float* __restrict__ brightness_f) {
    const int img = blockIdx.x / BLOCKS_PER_IMG;
    const int p4  = (blockIdx.x % BLOCKS_PER_IMG) * THREADS + threadIdx.x;

    const float4* base = (const float4*)(x + (size_t)img * 3 * HW);
    const float bf = brightness_f[img];

    float4 r4 = base[p4];
    float4 g4 = base[p4 + PIX4];
    float4 b4 = base[p4 + 2 * PIX4];

    float s = 0.0f;
    {
        float r = __saturatef(r4.x * bf), g = __saturatef(g4.x * bf), b = __saturatef(b4.x * bf);
        s += fmaf(0.114f, b, fmaf(0.587f, g, 0.299f * r));
        r = __saturatef(r4.y * bf); g = __saturatef(g4.y * bf); b = __saturatef(b4.y * bf);
        s += fmaf(0.114f, b, fmaf(0.587f, g, 0.299f * r));
        r = __saturatef(r4.z * bf); g = __saturatef(g4.z * bf); b = __saturatef(b4.z * bf);
        s += fmaf(0.114f, b, fmaf(0.587f, g, 0.299f * r));
        r = __saturatef(r4.w * bf); g = __saturatef(g4.w * bf); b = __saturatef(b4.w * bf);
        s += fmaf(0.114f, b, fmaf(0.587f, g, 0.299f * r));
    }

    // warp reduce
    #pragma unroll
    for (int off = 16; off > 0; off >>= 1)
        s += __shfl_down_sync(0xFFFFFFFFu, s, off);

    __shared__ float warp_sums[THREADS / 32];
    const int lane = threadIdx.x & 31;
    const int wid  = threadIdx.x >> 5;
    if (lane == 0) warp_sums[wid] = s;
    __syncthreads();

    if (wid == 0) {
        float v = (lane < THREADS / 32) ? warp_sums[lane] : 0.0f;
        #pragma unroll
        for (int off = 4; off > 0; off >>= 1)
            v += __shfl_down_sync(0xFFFFFFFFu, v, off);
        if (lane == 0) g_partial[blockIdx.x] = v;
    }
}

// ---------------------------------------------------------------------------
// Pass 2: full pipeline per pixel.
//   - x reads:   __ldcs (evict-first after single use, frees L2 as we go)
//   - out writes: __stwt (write-through, no L2 allocation -> no x eviction)
// ---------------------------------------------------------------------------
__global__ void __launch_bounds__(THREADS)
color_kernel(const float* __restrict__ x,
             const float* __restrict__ brightness_f,
             const float* __restrict__ contrast_f,
             const float* __restrict__ saturation_f,
             const float* __restrict__ hue_f,
             float* __restrict__ out) {
    const int rb  = GRID - 1 - blockIdx.x;           // reversed block id
    const int img = rb / BLOCKS_PER_IMG;
    const int p4  = (rb % BLOCKS_PER_IMG) * THREADS + threadIdx.x;

    const size_t img_off = (size_t)img * 3 * HW;
    const float4* src = (const float4*)(x + img_off);
    float4* dst = (float4*)(out + img_off);

    // ---- per-image mean from partials (all L2-hit) ----
    __shared__ float warp_sums[THREADS / 32];
    __shared__ float s_mean;
    {
        const float* part = g_partial + img * BLOCKS_PER_IMG;
        float v = 0.0f;
        for (int t = threadIdx.x; t < BLOCKS_PER_IMG; t += THREADS)
            v += part[t];
        #pragma unroll
        for (int off = 16; off > 0; off >>= 1)
            v += __shfl_down_sync(0xFFFFFFFFu, v, off);
        const int lane = threadIdx.x & 31;
        const int wid  = threadIdx.x >> 5;
        if (lane == 0) warp_sums[wid] = v;
        __syncthreads();
        if (threadIdx.x == 0) {
            float m = 0.0f;
            #pragma unroll
            for (int w = 0; w < THREADS / 32; w++) m += warp_sums[w];
            s_mean = m * (1.0f / (float)HW);
        }
        __syncthreads();
    }

    const float bf = brightness_f[img];
    const float cf = contrast_f[img];
    const float sf = saturation_f[img];
    const float hf6 = 6.0f * hue_f[img];       // hue shift in h6 domain
    const float cm   = (1.0f - cf) * s_mean;   // contrast blend constant
    const float omsf = 1.0f - sf;              // saturation blend coeff

    float4 r4 = __ldcs(&src[p4]);
    float4 g4 = __ldcs(&src[p4 + PIX4]);
    float4 b4 = __ldcs(&src[p4 + 2 * PIX4]);

    float ro[4], go[4], bo[4];
    const float* rp = &r4.x;
    const float* gp = &g4.x;
    const float* bp = &b4.x;

    #pragma unroll
    for (int k = 0; k < 4; k++) {
        // brightness (FMUL.SAT)
        float r = __saturatef(rp[k] * bf);
        float g = __saturatef(gp[k] * bf);
        float b = __saturatef(bp[k] * bf);
        // contrast blend with scalar mean (FFMA.SAT)
        r = __saturatef(fmaf(cf, r, cm));
        g = __saturatef(fmaf(cf, g, cm));
        b = __saturatef(fmaf(cf, b, cm));
        // saturation blend with per-pixel gray (FFMA.SAT)
        float gray = fmaf(0.114f, b, fmaf(0.587f, g, 0.299f * r));
        float sg = omsf * gray;
        r = __saturatef(fmaf(sf, r, sg));
        g = __saturatef(fmaf(sf, g, sg));
        b = __saturatef(fmaf(sf, b, sg));

        // ---- hue ----
        float maxc = fmaxf(r, fmaxf(g, b));
        float minc = fminf(r, fminf(g, b));
        float chroma = maxc - minc;
        float crd = (chroma == 0.0f) ? 1.0f : chroma;
        float rcp = __fdividef(1.0f, crd);

        float hr;                                 // raw hue * 6, in (-1, 5)
        if (maxc == r)      hr = (g - b) * rcp;
        else if (maxc == g) hr = fmaf(b - r, rcp, 2.0f);
        else                hr = fmaf(r - g, rcp, 4.0f);

        // h6 = (hr + 6*hf) mod 6; range of (hr + hf6) is (-2.8, 6.8)
        float h6 = hr + hf6;
        if (h6 < 0.0f)       h6 += 6.0f;
        else if (h6 >= 6.0f) h6 -= 6.0f;

        // triangular channel responses (branch-free; verified identical to
        // the reference's p/q/t sector table across all 6 sectors)
        float dr = fabsf(h6 - 3.0f);
        float fr = __saturatef(2.0f - dr);

        float tg = fabsf(h6 - 5.0f);
        float fg = __saturatef(2.0f - fminf(tg, 6.0f - tg));

        float tb = fabsf(h6 - 1.0f);
        float fb = __saturatef(2.0f - fminf(tb, 6.0f - tb));

        ro[k] = fmaf(-chroma, fr, maxc);
        go[k] = fmaf(-chroma, fg, maxc);
        bo[k] = fmaf(-chroma, fb, maxc);
    }

    // write-through streaming stores: no L2 allocation, keep x resident
    __stwt(&dst[p4],            make_float4(ro[0], ro[1], ro[2], ro[3]));
    __stwt(&dst[p4 + PIX4],     make_float4(go[0], go[1], go[2], go[3]));
    __stwt(&dst[p4 + 2 * PIX4], make_float4(bo[0], bo[1], bo[2], bo[3]));
}

extern "C" void kernel_launch(void* const* d_in, const int* in_sizes, int n_in,
                              void* d_out, int out_size) {
    const float* x  = (const float*)d_in[0];
    const float* bf = (const float*)d_in[1];
    const float* cf = (const float*)d_in[2];
    const float* sf = (const float*)d_in[3];
    const float* hf = (const float*)d_in[4];
    float* out = (float*)d_out;

    reduce_mean_kernel<<<GRID, THREADS>>>(x, bf);
    color_kernel<<<GRID, THREADS>>>(x, bf, cf, sf, hf, out);
}

// round 9
// speedup vs baseline: 1.1066x; 1.1066x over previous
#include <cuda_runtime.h>

// Problem constants
#define NB 32
#define NH 480
#define NW 640
#define HW (NH * NW)            // 307200 pixels per channel plane
#define PIX4 (HW / 4)           // 76800 float4 pixels per plane
#define THREADS 256
#define BLOCKS_PER_IMG (PIX4 / THREADS)   // 300
#define GRID (NB * BLOCKS_PER_IMG)        // 9600

// Per-block partial sums — every slot is written every launch, no init needed.
__device__ float g_partial[GRID];

// ---------------------------------------------------------------------------
// Pass 1: per-block partial sum of gray(clip(x * bf)).
// Triggers programmatic launch of color_kernel as blocks complete.
// ---------------------------------------------------------------------------
__global__ void __launch_bounds__(THREADS)
reduce_mean_kernel(const float* __restrict__ x,
                   const float* __restrict__ brightness_f) {
    const int img = blockIdx.x / BLOCKS_PER_IMG;
    const int p4  = (blockIdx.x % BLOCKS_PER_IMG) * THREADS + threadIdx.x;

    const float4* base = (const float4*)(x + (size_t)img * 3 * HW);
    const float bf = brightness_f[img];

    float4 r4 = base[p4];
    float4 g4 = base[p4 + PIX4];
    float4 b4 = base[p4 + 2 * PIX4];

    float s = 0.0f;
    {
        float r = __saturatef(r4.x * bf), g = __saturatef(g4.x * bf), b = __saturatef(b4.x * bf);
        s += fmaf(0.114f, b, fmaf(0.587f, g, 0.299f * r));
        r = __saturatef(r4.y * bf); g = __saturatef(g4.y * bf); b = __saturatef(b4.y * bf);
        s += fmaf(0.114f, b, fmaf(0.587f, g, 0.299f * r));
        r = __saturatef(r4.z * bf); g = __saturatef(g4.z * bf); b = __saturatef(b4.z * bf);
        s += fmaf(0.114f, b, fmaf(0.587f, g, 0.299f * r));
        r = __saturatef(r4.w * bf); g = __saturatef(g4.w * bf); b = __saturatef(b4.w * bf);
        s += fmaf(0.114f, b, fmaf(0.587f, g, 0.299f * r));
    }

    // warp reduce
    #pragma unroll
    for (int off = 16; off > 0; off >>= 1)
        s += __shfl_down_sync(0xFFFFFFFFu, s, off);

    __shared__ float warp_sums[THREADS / 32];
    const int lane = threadIdx.x & 31;
    const int wid  = threadIdx.x >> 5;
    if (lane == 0) warp_sums[wid] = s;
    __syncthreads();

    if (wid == 0) {
        float v = (lane < THREADS / 32) ? warp_sums[lane] : 0.0f;
        #pragma unroll
        for (int off = 4; off > 0; off >>= 1)
            v += __shfl_down_sync(0xFFFFFFFFu, v, off);
        if (lane == 0) g_partial[blockIdx.x] = v;
    }

    // Allow the dependent color_kernel grid to begin launching.
    cudaTriggerProgrammaticLaunchCompletion();
}

// ---------------------------------------------------------------------------
// Pass 2: full pipeline per pixel. Launched with PDL: x-loads are issued
// BEFORE cudaGridDependencySynchronize(); only the mean read waits on pass 1.
// ---------------------------------------------------------------------------
__global__ void __launch_bounds__(THREADS)
color_kernel(const float* __restrict__ x,
             const float* __restrict__ brightness_f,
             const float* __restrict__ contrast_f,
             const float* __restrict__ saturation_f,
             const float* __restrict__ hue_f,
             float* __restrict__ out) {
    const int rb  = GRID - 1 - blockIdx.x;           // reversed block id
    const int img = rb / BLOCKS_PER_IMG;
    const int p4  = (rb % BLOCKS_PER_IMG) * THREADS + threadIdx.x;

    const size_t img_off = (size_t)img * 3 * HW;
    const float4* src = (const float4*)(x + img_off);
    float4* dst = (float4*)(out + img_off);

    // Issue independent x loads first (overlap with reduce tail under PDL).
    float4 r4 = src[p4];
    float4 g4 = src[p4 + PIX4];
    float4 b4 = src[p4 + 2 * PIX4];

    const float bf  = brightness_f[img];
    const float cf  = contrast_f[img];
    const float sf  = saturation_f[img];
    const float hf6 = 6.0f * hue_f[img];       // hue shift in h6 domain

    // Wait for the reduce grid before touching g_partial.
    cudaGridDependencySynchronize();

    // ---- per-image mean from partials (all L2-hit) ----
    __shared__ float warp_sums[THREADS / 32];
    __shared__ float s_mean;
    {
        const float* part = g_partial + img * BLOCKS_PER_IMG;
        float v = 0.0f;
        for (int t = threadIdx.x; t < BLOCKS_PER_IMG; t += THREADS)
            v += part[t];
        #pragma unroll
        for (int off = 16; off > 0; off >>= 1)
            v += __shfl_down_sync(0xFFFFFFFFu, v, off);
        const int lane = threadIdx.x & 31;
        const int wid  = threadIdx.x >> 5;
        if (lane == 0) warp_sums[wid] = v;
        __syncthreads();
        if (threadIdx.x == 0) {
            float m = 0.0f;
            #pragma unroll
            for (int w = 0; w < THREADS / 32; w++) m += warp_sums[w];
            s_mean = m * (1.0f / (float)HW);
        }
        __syncthreads();
    }

    const float cm   = (1.0f - cf) * s_mean;   // contrast blend constant
    const float omsf = 1.0f - sf;              // saturation blend coeff

    float ro[4], go[4], bo[4];
    const float* rp = &r4.x;
    const float* gp = &g4.x;
    const float* bp = &b4.x;

    #pragma unroll
    for (int k = 0; k < 4; k++) {
        // brightness (FMUL.SAT)
        float r = __saturatef(rp[k] * bf);
        float g = __saturatef(gp[k] * bf);
        float b = __saturatef(bp[k] * bf);
        // contrast blend with scalar mean (FFMA.SAT)
        r = __saturatef(fmaf(cf, r, cm));
        g = __saturatef(fmaf(cf, g, cm));
        b = __saturatef(fmaf(cf, b, cm));
        // saturation blend with per-pixel gray (FFMA.SAT)
        float gray = fmaf(0.114f, b, fmaf(0.587f, g, 0.299f * r));
        float sg = omsf * gray;
        r = __saturatef(fmaf(sf, r, sg));
        g = __saturatef(fmaf(sf, g, sg));
        b = __saturatef(fmaf(sf, b, sg));

        // ---- hue ----
        float maxc = fmaxf(r, fmaxf(g, b));
        float minc = fminf(r, fminf(g, b));
        float chroma = maxc - minc;
        float crd = (chroma == 0.0f) ? 1.0f : chroma;
        float rcp = __fdividef(1.0f, crd);

        float hr;                                 // raw hue * 6, in (-1, 5)
        if (maxc == r)      hr = (g - b) * rcp;
        else if (maxc == g) hr = fmaf(b - r, rcp, 2.0f);
        else                hr = fmaf(r - g, rcp, 4.0f);

        // h6 = (hr + 6*hf) mod 6; range of (hr + hf6) is (-2.8, 6.8)
        float h6 = hr + hf6;
        if (h6 < 0.0f)       h6 += 6.0f;
        else if (h6 >= 6.0f) h6 -= 6.0f;

        // triangular channel responses (branch-free; verified identical to
        // the reference's p/q/t sector table across all 6 sectors)
        float dr = fabsf(h6 - 3.0f);
        float fr = __saturatef(2.0f - dr);

        float tg = fabsf(h6 - 5.0f);
        float fg = __saturatef(2.0f - fminf(tg, 6.0f - tg));

        float tb = fabsf(h6 - 1.0f);
        float fb = __saturatef(2.0f - fminf(tb, 6.0f - tb));

        ro[k] = fmaf(-chroma, fr, maxc);
        go[k] = fmaf(-chroma, fg, maxc);
        bo[k] = fmaf(-chroma, fb, maxc);
    }

    __stcs(&dst[p4],            make_float4(ro[0], ro[1], ro[2], ro[3]));
    __stcs(&dst[p4 + PIX4],     make_float4(go[0], go[1], go[2], go[3]));
    __stcs(&dst[p4 + 2 * PIX4], make_float4(bo[0], bo[1], bo[2], bo[3]));
}

extern "C" void kernel_launch(void* const* d_in, const int* in_sizes, int n_in,
                              void* d_out, int out_size) {
    const float* x  = (const float*)d_in[0];
    const float* bf = (const float*)d_in[1];
    const float* cf = (const float*)d_in[2];
    const float* sf = (const float*)d_in[3];
    const float* hf = (const float*)d_in[4];
    float* out = (float*)d_out;

    reduce_mean_kernel<<<GRID, THREADS>>>(x, bf);

    // Launch color_kernel with Programmatic Dependent Launch so its x-loads
    // overlap the reduce kernel's tail. Falls back to a plain launch on error
    // (cudaGridDependencySynchronize is a no-op for non-PDL launches).
    cudaLaunchConfig_t cfg = {};
    cfg.gridDim  = dim3(GRID, 1, 1);
    cfg.blockDim = dim3(THREADS, 1, 1);
    cfg.dynamicSmemBytes = 0;
    cudaLaunchAttribute attr[1];
    attr[0].id = cudaLaunchAttributeProgrammaticStreamSerialization;
    attr[0].val.programmaticStreamSerializationAllowed = 1;
    cfg.attrs = attr;
    cfg.numAttrs = 1;

    cudaError_t e = cudaLaunchKernelEx(&cfg, color_kernel, x, bf, cf, sf, hf, out);
    if (e != cudaSuccess) {
        color_kernel<<<GRID, THREADS>>>(x, bf, cf, sf, hf, out);
    }
}